// round 1
// baseline (speedup 1.0000x reference)
#include <cuda_runtime.h>
#include <math.h>

#define NN 2048
#define MM 128
#define KD 8
#define K2 64

// ---------------- scratch (device globals; no allocations allowed) ----------
// per-parent (SoA over m for coalesced pair-kernel loads)
__device__ float g_B[2][K2][MM];   // B = Omega_p^T Sigma_p^{-1} Omega_p (row-major idx)
__device__ float g_G[2][K2][MM];   // G = L_p^{-1} Omega_p
__device__ float g_e[2][KD][MM];   // e = L_p^{-1} mu_p
__device__ float g_d[2][MM];       // logdet Sigma_p - 2 log|det Omega_p|
// per-child (AoS; one block reads one child's record into shared)
__device__ float g_A[2][NN][K2];   // A = Oc^{-1} Sigma_c Oc^{-T}
__device__ float g_v[2][NN][KD];   // v = Oc^{-1} mu_c
__device__ float g_c[2][NN];       // 2 log|det Oc| - logdet Sigma_c
__device__ double g_acc[2];

__global__ void zero_acc_kernel() {
    if (threadIdx.x < 2) g_acc[threadIdx.x] = 0.0;
}

// -------------------- per-parent precompute: one thread per (t, m) ----------
__global__ void parent_kernel(const float* __restrict__ mup0, const float* __restrict__ Sp0,
                              const float* __restrict__ Op0,
                              const float* __restrict__ mup1, const float* __restrict__ Sp1,
                              const float* __restrict__ Op1) {
    int t = blockIdx.x;
    int m = threadIdx.x;
    const float* mup = (t == 0) ? mup0 : mup1;
    const float* Sp  = (t == 0) ? Sp0  : Sp1;
    const float* Opp = (t == 0) ? Op0  : Op1;

    float S[KD][KD], L[KD][KD], O[KD][KD], G[KD][KD];
    for (int i = 0; i < KD; i++)
        for (int j = 0; j < KD; j++) {
            S[i][j] = Sp[m * K2 + i * KD + j];
            O[i][j] = Opp[m * K2 + i * KD + j];
        }

    // Cholesky S = L L^T, accumulate logdet
    float ldSp = 0.f;
    for (int j = 0; j < KD; j++) {
        float s = S[j][j];
        for (int k = 0; k < j; k++) s -= L[j][k] * L[j][k];
        float ljj = sqrtf(s);
        L[j][j] = ljj;
        ldSp += 2.f * logf(ljj);
        float inv = 1.f / ljj;
        for (int i = j + 1; i < KD; i++) {
            float si = S[i][j];
            for (int k = 0; k < j; k++) si -= L[i][k] * L[j][k];
            L[i][j] = si * inv;
        }
    }

    // G = L^{-1} O (forward substitution per column)
    for (int c = 0; c < KD; c++) {
        for (int i = 0; i < KD; i++) {
            float s = O[i][c];
            for (int k = 0; k < i; k++) s -= L[i][k] * G[k][c];
            G[i][c] = s / L[i][i];
        }
    }
    // e = L^{-1} mu_p
    float e[KD];
    for (int i = 0; i < KD; i++) {
        float s = mup[m * KD + i];
        for (int k = 0; k < i; k++) s -= L[i][k] * e[k];
        e[i] = s / L[i][i];
    }

    // log|det O| via LU with partial pivoting (destroys O)
    float lad = 0.f;
    for (int j = 0; j < KD; j++) {
        int p = j; float mx = fabsf(O[j][j]);
        for (int r = j + 1; r < KD; r++) {
            float a = fabsf(O[r][j]);
            if (a > mx) { mx = a; p = r; }
        }
        if (p != j)
            for (int c = 0; c < KD; c++) { float tmp = O[j][c]; O[j][c] = O[p][c]; O[p][c] = tmp; }
        float piv = O[j][j];
        lad += logf(fabsf(piv));
        float ip = 1.f / piv;
        for (int r = j + 1; r < KD; r++) {
            float f = O[r][j] * ip;
            for (int c = j + 1; c < KD; c++) O[r][c] -= f * O[j][c];
        }
    }

    // store SoA
    for (int i = 0; i < KD; i++)
        for (int j = 0; j < KD; j++) {
            g_G[t][i * KD + j][m] = G[i][j];
            float b = 0.f;
            for (int k = 0; k < KD; k++) b += G[k][i] * G[k][j];
            g_B[t][i * KD + j][m] = b;
        }
    for (int i = 0; i < KD; i++) g_e[t][i][m] = e[i];
    g_d[t][m] = ldSp - 2.f * lad;
}

// -------------------- per-child precompute: one thread per (t, n) -----------
__global__ void child_kernel(const float* __restrict__ muc0, const float* __restrict__ S00,
                             const float* __restrict__ Oc0,
                             const float* __restrict__ muc1, const float* __restrict__ S01,
                             const float* __restrict__ Oc1) {
    int gid = blockIdx.x * blockDim.x + threadIdx.x;
    if (gid >= 2 * NN) return;
    int t = gid / NN;
    int n = gid % NN;
    const float* muc = (t == 0) ? muc0 : muc1;
    const float* S0p = (t == 0) ? S00  : S01;
    const float* Ocp = (t == 0) ? Oc0  : Oc1;

    float O[KD][KD], Oi[KD][KD], S[KD][KD];
    for (int i = 0; i < KD; i++)
        for (int j = 0; j < KD; j++) {
            O[i][j]  = Ocp[n * K2 + i * KD + j];
            S[i][j]  = S0p[n * K2 + i * KD + j];
            Oi[i][j] = (i == j) ? 1.f : 0.f;
        }

    // Gauss-Jordan inverse with partial pivoting; track log|det|
    float lad = 0.f;
    for (int j = 0; j < KD; j++) {
        int p = j; float mx = fabsf(O[j][j]);
        for (int r = j + 1; r < KD; r++) {
            float a = fabsf(O[r][j]);
            if (a > mx) { mx = a; p = r; }
        }
        if (p != j) {
            for (int c = 0; c < KD; c++) {
                float tt = O[j][c];  O[j][c]  = O[p][c];  O[p][c]  = tt;
                tt = Oi[j][c]; Oi[j][c] = Oi[p][c]; Oi[p][c] = tt;
            }
        }
        float piv = O[j][j];
        lad += logf(fabsf(piv));
        float ip = 1.f / piv;
        for (int c = 0; c < KD; c++) { O[j][c] *= ip; Oi[j][c] *= ip; }
        for (int r = 0; r < KD; r++) {
            if (r == j) continue;
            float f = O[r][j];
            for (int c = 0; c < KD; c++) { O[r][c] -= f * O[j][c]; Oi[r][c] -= f * Oi[j][c]; }
        }
    }

    // v = Oi * mu_c
    float mu[KD];
    for (int i = 0; i < KD; i++) mu[i] = muc[n * KD + i];
    for (int i = 0; i < KD; i++) {
        float s = 0.f;
        for (int j = 0; j < KD; j++) s += Oi[i][j] * mu[j];
        g_v[t][n][i] = s;
    }

    // A = Oi * S * Oi^T
    for (int i = 0; i < KD; i++) {
        float trow[KD];
        for (int c = 0; c < KD; c++) {
            float s = 0.f;
            for (int b = 0; b < KD; b++) s += Oi[i][b] * S[b][c];
            trow[c] = s;
        }
        for (int j = 0; j < KD; j++) {
            float s = 0.f;
            for (int c = 0; c < KD; c++) s += trow[c] * Oi[j][c];
            g_A[t][n][i * KD + j] = s;
        }
    }

    // logdet Sigma_c via in-place lower Cholesky
    float ld0 = 0.f;
    for (int j = 0; j < KD; j++) {
        float s = S[j][j];
        for (int k = 0; k < j; k++) s -= S[j][k] * S[j][k];
        float ljj = sqrtf(s);
        S[j][j] = ljj;
        ld0 += 2.f * logf(ljj);
        float inv = 1.f / ljj;
        for (int i = j + 1; i < KD; i++) {
            float si = S[i][j];
            for (int k = 0; k < j; k++) si -= S[i][k] * S[j][k];
            S[i][j] = si * inv;
        }
    }
    g_c[t][n] = 2.f * lad - ld0;
}

// -------------------- pair kernel: block = (t, n); thread = m ---------------
__global__ void pair_kernel(const float* __restrict__ W) {
    int t = blockIdx.y;
    int n = blockIdx.x;
    int m = threadIdx.x;

    __shared__ float Ash[K2];
    __shared__ float vsh[KD];
    __shared__ float csh;
    __shared__ double wsum[4];

    if (m < K2) Ash[m] = g_A[t][n][m];
    else if (m < K2 + KD) vsh[m - K2] = g_v[t][n][m - K2];
    else if (m == K2 + KD) csh = g_c[t][n];
    __syncthreads();

    float v[KD];
#pragma unroll
    for (int j = 0; j < KD; j++) v[j] = vsh[j];

    float tr = 0.f;
#pragma unroll
    for (int idx = 0; idx < K2; idx++) tr += g_B[t][idx][m] * Ash[idx];

    float maha = 0.f;
#pragma unroll
    for (int i = 0; i < KD; i++) {
        float s = g_e[t][i][m];
#pragma unroll
        for (int j = 0; j < KD; j++) s -= g_G[t][i * KD + j][m] * v[j];
        maha += s * s;
    }

    float kl = 0.5f * (tr + maha - (float)KD + g_d[t][m] + csh);
    double val = (double)(W[n * MM + m] * kl);

#pragma unroll
    for (int off = 16; off; off >>= 1)
        val += __shfl_down_sync(0xffffffffu, val, off);
    int lane = m & 31, warp = m >> 5;
    if (lane == 0) wsum[warp] = val;
    __syncthreads();
    if (m == 0) atomicAdd(&g_acc[t], wsum[0] + wsum[1] + wsum[2] + wsum[3]);
}

__global__ void finalize_kernel(float* out) {
    double b = g_acc[0], mo = g_acc[1];
    out[0] = (float)(b + mo);
    out[1] = (float)b;
    out[2] = (float)mo;
}

// ----------------------------------------------------------------------------
extern "C" void kernel_launch(void* const* d_in, const int* in_sizes, int n_in,
                              void* d_out, int out_size) {
    const float* W              = (const float*)d_in[0];
    const float* mu_p           = (const float*)d_in[1];
    const float* sigma_p        = (const float*)d_in[2];
    const float* mu_q_parent    = (const float*)d_in[3];
    const float* sigma_q_parent = (const float*)d_in[4];
    const float* omega_child    = (const float*)d_in[5];
    const float* omega_parent   = (const float*)d_in[6];
    const float* mu_r           = (const float*)d_in[7];
    const float* sigma_r        = (const float*)d_in[8];
    const float* mu_s_parent    = (const float*)d_in[9];
    const float* sigma_s_parent = (const float*)d_in[10];
    const float* omega_m_child  = (const float*)d_in[11];
    const float* omega_m_parent = (const float*)d_in[12];

    zero_acc_kernel<<<1, 32>>>();
    parent_kernel<<<2, MM>>>(mu_q_parent, sigma_q_parent, omega_parent,
                             mu_s_parent, sigma_s_parent, omega_m_parent);
    child_kernel<<<(2 * NN + 127) / 128, 128>>>(mu_p, sigma_p, omega_child,
                                                mu_r, sigma_r, omega_m_child);
    pair_kernel<<<dim3(NN, 2), MM>>>(W);
    finalize_kernel<<<1, 1>>>((float*)d_out);
}

// round 2
// speedup vs baseline: 3.1425x; 3.1425x over previous
#include <cuda_runtime.h>
#include <math.h>

#define NN 2048
#define MM 128
#define KD 8
#define K2 64
#define NPACK 36          // packed symmetric 8x8
#define CH_STRIDE 48      // per-child record: 36 A + 8 v + 1 c + 3 pad (16B aligned)
#define NB 128            // n-chunks per t
#define NPB (NN / NB)     // children per block = 16

// ---------------- scratch (device globals) ----------------------------------
__device__ float g_Bp[2][NPACK][MM];  // 0.5*w_ij * (G^T G)_ij packed, SoA over m
__device__ float g_Gs[2][K2][MM];     // G/sqrt(2), SoA over m
__device__ float g_es[2][KD][MM];     // e/sqrt(2), SoA over m
__device__ float g_dp[2][MM];         // -log|det G| - 4
__device__ float g_child[2][NN][CH_STRIDE]; // [A packed 36][v 8][c' 1][pad 3]
__device__ double g_acc[2];
__device__ unsigned int g_done;

// ==================== precompute: parents + children + zero =================
__device__ __forceinline__ void parent_work(int t, int m, const float* __restrict__ mup,
                                            const float* __restrict__ Sp,
                                            const float* __restrict__ Op) {
    float S[KD][KD], O[KD][KD], e[KD];
#pragma unroll
    for (int i = 0; i < KD; i++) {
#pragma unroll
        for (int j = 0; j < KD; j++) {
            S[i][j] = Sp[m * K2 + i * KD + j];
            O[i][j] = Op[m * K2 + i * KD + j];
        }
        e[i] = mup[m * KD + i];
    }
    // Cholesky in place (lower triangle of S becomes L)
#pragma unroll
    for (int j = 0; j < KD; j++) {
        float s = S[j][j];
#pragma unroll
        for (int k = 0; k < j; k++) s -= S[j][k] * S[j][k];
        float ljj = sqrtf(s);
        S[j][j] = ljj;
        float inv = 1.f / ljj;
#pragma unroll
        for (int i = j + 1; i < KD; i++) {
            float si = S[i][j];
#pragma unroll
            for (int k = 0; k < j; k++) si -= S[i][k] * S[j][k];
            S[i][j] = si * inv;
        }
    }
    // O := L^{-1} O (in place), e := L^{-1} e
#pragma unroll
    for (int i = 0; i < KD; i++) {
        float inv = 1.f / S[i][i];
#pragma unroll
        for (int c = 0; c < KD; c++) {
            float s = O[i][c];
#pragma unroll
            for (int k = 0; k < i; k++) s -= S[i][k] * O[k][c];
            O[i][c] = s * inv;
        }
        float se = e[i];
#pragma unroll
        for (int k = 0; k < i; k++) se -= S[i][k] * e[k];
        e[i] = se * inv;
    }
    const float rs = 0.70710678118654752f; // 1/sqrt(2)
#pragma unroll
    for (int i = 0; i < KD; i++) {
#pragma unroll
        for (int j = 0; j < KD; j++) g_Gs[t][i * KD + j][m] = O[i][j] * rs;
        g_es[t][i][m] = e[i] * rs;
    }
    // B = G^T G, packed with 0.5 (diag) / 1.0 (off-diag, folds the 2x)
    {
        int p = 0;
#pragma unroll
        for (int i = 0; i < KD; i++) {
#pragma unroll
            for (int j = i; j < KD; j++) {
                float b = 0.f;
#pragma unroll
                for (int k = 0; k < KD; k++) b += O[k][i] * O[k][j];
                g_Bp[t][p][m] = (i == j) ? 0.5f * b : b;
                p++;
            }
        }
    }
    // log|det G| via unpivoted LU (destroys O)
    float lad = 0.f;
#pragma unroll
    for (int j = 0; j < KD; j++) {
        float piv = O[j][j];
        lad += logf(fabsf(piv));
        float ip = 1.f / piv;
#pragma unroll
        for (int r = j + 1; r < KD; r++) {
            float f = O[r][j] * ip;
#pragma unroll
            for (int c = j + 1; c < KD; c++) O[r][c] -= f * O[j][c];
        }
    }
    g_dp[t][m] = -lad - 4.0f;
}

__device__ __forceinline__ void child_work(int t, int n, const float* __restrict__ muc,
                                           const float* __restrict__ Sc,
                                           const float* __restrict__ Oc) {
    float O[KD][KD], S[KD][KD];
#pragma unroll
    for (int i = 0; i < KD; i++)
#pragma unroll
        for (int j = 0; j < KD; j++) {
            O[i][j] = Oc[n * K2 + i * KD + j];
            S[i][j] = Sc[n * K2 + i * KD + j];
        }
    // in-place unpivoted Gauss-Jordan inverse; product of pivots = det
    float lad = 0.f;
#pragma unroll
    for (int k = 0; k < KD; k++) {
        float piv = O[k][k];
        lad += logf(fabsf(piv));
        float ip = 1.f / piv;
#pragma unroll
        for (int i = 0; i < KD; i++) {
            if (i == k) continue;
            float f = O[i][k] * ip;
#pragma unroll
            for (int j = 0; j < KD; j++)
                if (j != k) O[i][j] -= f * O[k][j];
            O[i][k] = -f;
        }
#pragma unroll
        for (int j = 0; j < KD; j++)
            if (j != k) O[k][j] *= ip;
        O[k][k] = ip;
    }
    float* out = &g_child[t][n][0];
    // v = Oi * mu
    float mu[KD];
#pragma unroll
    for (int i = 0; i < KD; i++) mu[i] = muc[n * KD + i];
#pragma unroll
    for (int i = 0; i < KD; i++) {
        float s = 0.f;
#pragma unroll
        for (int j = 0; j < KD; j++) s += O[i][j] * mu[j];
        out[NPACK + i] = s;
    }
    // A = Oi S Oi^T, packed upper (i<=j), same p-order as B
    {
        int p = 0;
#pragma unroll
        for (int i = 0; i < KD; i++) {
            float trow[KD];
#pragma unroll
            for (int c = 0; c < KD; c++) {
                float s = 0.f;
#pragma unroll
                for (int b = 0; b < KD; b++) s += O[i][b] * S[b][c];
                trow[c] = s;
            }
#pragma unroll
            for (int j = i; j < KD; j++) {
                float a = 0.f;
#pragma unroll
                for (int c = 0; c < KD; c++) a += trow[c] * O[j][c];
                out[p] = a;
                p++;
            }
        }
    }
    // logdet Sigma_c via in-place Cholesky on S
    float ld0 = 0.f;
#pragma unroll
    for (int j = 0; j < KD; j++) {
        float s = S[j][j];
#pragma unroll
        for (int k = 0; k < j; k++) s -= S[j][k] * S[j][k];
        float ljj = sqrtf(s);
        S[j][j] = ljj;
        ld0 += 2.f * logf(ljj);
        float inv = 1.f / ljj;
#pragma unroll
        for (int i = j + 1; i < KD; i++) {
            float si = S[i][j];
#pragma unroll
            for (int k = 0; k < j; k++) si -= S[i][k] * S[j][k];
            S[i][j] = si * inv;
        }
    }
    out[NPACK + KD] = lad - 0.5f * ld0;
    out[45] = 0.f; out[46] = 0.f; out[47] = 0.f;
}

__global__ __launch_bounds__(64)
void precompute_kernel(const float* __restrict__ mu_p, const float* __restrict__ sigma_p,
                       const float* __restrict__ omega_child,
                       const float* __restrict__ mu_q, const float* __restrict__ sigma_q,
                       const float* __restrict__ omega_parent,
                       const float* __restrict__ mu_r, const float* __restrict__ sigma_r,
                       const float* __restrict__ omega_m_child,
                       const float* __restrict__ mu_s, const float* __restrict__ sigma_s,
                       const float* __restrict__ omega_m_parent) {
    int bid = blockIdx.x;
    int tid = threadIdx.x;
    if (bid == 0 && tid == 0) {
        g_acc[0] = 0.0;
        g_acc[1] = 0.0;
        g_done = 0u;
    }
    if (bid < 4) {
        // parent work: 4 blocks x 64 threads = 256 = 2 t x 128 m
        int t = bid >> 1;
        int m = ((bid & 1) << 6) + tid;
        if (t == 0) parent_work(0, m, mu_q, sigma_q, omega_parent);
        else        parent_work(1, m, mu_s, sigma_s, omega_m_parent);
    } else {
        int gid = (bid - 4) * 64 + tid;   // 64 blocks x 64 = 4096 = 2 t x 2048 n
        int t = gid >> 11;
        int n = gid & (NN - 1);
        if (t == 0) child_work(0, n, mu_p, sigma_p, omega_child);
        else        child_work(1, n, mu_r, sigma_r, omega_m_child);
    }
}

// ==================== pair kernel + fused finalize ===========================
__global__ __launch_bounds__(128)
void pair_kernel(const float* __restrict__ W, float* __restrict__ out) {
    const int t = blockIdx.y;
    const int m = threadIdx.x;
    const int n0 = blockIdx.x * NPB;

    // per-m data resident in registers
    float Bp[NPACK], Gs[K2], es[KD], dp;
#pragma unroll
    for (int p = 0; p < NPACK; p++) Bp[p] = g_Bp[t][p][m];
#pragma unroll
    for (int p = 0; p < K2; p++) Gs[p] = g_Gs[t][p][m];
#pragma unroll
    for (int p = 0; p < KD; p++) es[p] = g_es[t][p][m];
    dp = g_dp[t][m];

    __shared__ float4 Abuf[2][CH_STRIDE / 4];

    // preload first child record
    if (m < CH_STRIDE / 4)
        Abuf[0][m] = reinterpret_cast<const float4*>(&g_child[t][n0][0])[m];
    __syncthreads();

    double acc = 0.0;
#pragma unroll 2
    for (int k = 0; k < NPB; k++) {
        int cur = k & 1;
        if (k + 1 < NPB && m < CH_STRIDE / 4)
            Abuf[cur ^ 1][m] =
                reinterpret_cast<const float4*>(&g_child[t][n0 + k + 1][0])[m];

        const float* A = reinterpret_cast<const float*>(&Abuf[cur][0]);
        float v[KD];
#pragma unroll
        for (int j = 0; j < KD; j++) v[j] = A[NPACK + j];

        float kl = dp + A[NPACK + KD];  // d' + c'
#pragma unroll
        for (int p = 0; p < NPACK; p++) kl += Bp[p] * A[p];  // 0.5*tr(B A)
#pragma unroll
        for (int i = 0; i < KD; i++) {
            float s = es[i];
#pragma unroll
            for (int j = 0; j < KD; j++) s -= Gs[i * KD + j] * v[j];
            kl += s * s;                 // 0.5*maha
        }
        float w = W[(size_t)(n0 + k) * MM + m];
        acc += (double)(w * kl);
        __syncthreads();
    }

    // block reduction (4 warps)
    __shared__ double wsum[4];
#pragma unroll
    for (int off = 16; off; off >>= 1)
        acc += __shfl_down_sync(0xffffffffu, acc, off);
    if ((m & 31) == 0) wsum[m >> 5] = acc;
    __syncthreads();
    if (m == 0) {
        double bsum = wsum[0] + wsum[1] + wsum[2] + wsum[3];
        atomicAdd(&g_acc[t], bsum);
        __threadfence();
        unsigned int tick = atomicAdd(&g_done, 1u);
        if (tick == 2u * NB - 1u) {
            __threadfence();
            double b  = *((volatile double*)&g_acc[0]);
            double mo = *((volatile double*)&g_acc[1]);
            out[0] = (float)(b + mo);
            out[1] = (float)b;
            out[2] = (float)mo;
        }
    }
}

// ----------------------------------------------------------------------------
extern "C" void kernel_launch(void* const* d_in, const int* in_sizes, int n_in,
                              void* d_out, int out_size) {
    const float* W              = (const float*)d_in[0];
    const float* mu_p           = (const float*)d_in[1];
    const float* sigma_p        = (const float*)d_in[2];
    const float* mu_q_parent    = (const float*)d_in[3];
    const float* sigma_q_parent = (const float*)d_in[4];
    const float* omega_child    = (const float*)d_in[5];
    const float* omega_parent   = (const float*)d_in[6];
    const float* mu_r           = (const float*)d_in[7];
    const float* sigma_r        = (const float*)d_in[8];
    const float* mu_s_parent    = (const float*)d_in[9];
    const float* sigma_s_parent = (const float*)d_in[10];
    const float* omega_m_child  = (const float*)d_in[11];
    const float* omega_m_parent = (const float*)d_in[12];

    precompute_kernel<<<68, 64>>>(mu_p, sigma_p, omega_child,
                                  mu_q_parent, sigma_q_parent, omega_parent,
                                  mu_r, sigma_r, omega_m_child,
                                  mu_s_parent, sigma_s_parent, omega_m_parent);
    pair_kernel<<<dim3(NB, 2), MM>>>(W, (float*)d_out);
}

// round 3
// speedup vs baseline: 4.4833x; 1.4267x over previous
#include <cuda_runtime.h>
#include <math.h>

#define NN 2048
#define MM 128
#define KD 8
#define K2 64
#define NPACK 36          // packed symmetric 8x8 (i<=j)
#define CH_STRIDE 48      // per-child record: 36 Atilde + 8 v + 1 c' + 3 pad
#define NPB 4             // children per block
#define NB (NN / NPB)     // 512 n-chunks per t

// ---------------- scratch (device globals) ----------------------------------
__device__ float g_Bp[2][NPACK][MM];  // packed G^T G with 0.5 diag / 1.0 offdiag, SoA over m
__device__ float g_h[2][KD][MM];      // h = G^T e, SoA over m
__device__ float g_dm[2][MM];         // -log|det G| - 4 + 0.5 e.e
__device__ float g_child[2][NN][CH_STRIDE];
__device__ double g_acc[2];
__device__ unsigned int g_done;

// ==================== precompute =============================================
__device__ __forceinline__ void parent_work(int t, int m, const float* __restrict__ mup,
                                            const float* __restrict__ Sp,
                                            const float* __restrict__ Op) {
    float S[KD][KD], O[KD][KD], e[KD];
#pragma unroll
    for (int i = 0; i < KD; i++) {
#pragma unroll
        for (int j = 0; j < KD; j++) {
            S[i][j] = Sp[m * K2 + i * KD + j];
            O[i][j] = Op[m * K2 + i * KD + j];
        }
        e[i] = mup[m * KD + i];
    }
    // Cholesky in place (lower triangle of S becomes L)
#pragma unroll
    for (int j = 0; j < KD; j++) {
        float s = S[j][j];
#pragma unroll
        for (int k = 0; k < j; k++) s -= S[j][k] * S[j][k];
        float ljj = sqrtf(s);
        S[j][j] = ljj;
        float inv = 1.f / ljj;
#pragma unroll
        for (int i = j + 1; i < KD; i++) {
            float si = S[i][j];
#pragma unroll
            for (int k = 0; k < j; k++) si -= S[i][k] * S[j][k];
            S[i][j] = si * inv;
        }
    }
    // O := G = L^{-1} O (in place), e := L^{-1} e
#pragma unroll
    for (int i = 0; i < KD; i++) {
        float inv = 1.f / S[i][i];
#pragma unroll
        for (int c = 0; c < KD; c++) {
            float s = O[i][c];
#pragma unroll
            for (int k = 0; k < i; k++) s -= S[i][k] * O[k][c];
            O[i][c] = s * inv;
        }
        float se = e[i];
#pragma unroll
        for (int k = 0; k < i; k++) se -= S[i][k] * e[k];
        e[i] = se * inv;
    }
    // B = G^T G, packed 0.5 diag / 1.0 offdiag; h = G^T e; ee = e.e
    {
        int p = 0;
#pragma unroll
        for (int i = 0; i < KD; i++) {
#pragma unroll
            for (int j = i; j < KD; j++) {
                float b = 0.f;
#pragma unroll
                for (int k = 0; k < KD; k++) b += O[k][i] * O[k][j];
                g_Bp[t][p][m] = (i == j) ? 0.5f * b : b;
                p++;
            }
        }
    }
    float ee = 0.f;
#pragma unroll
    for (int i = 0; i < KD; i++) {
        float s = 0.f;
#pragma unroll
        for (int k = 0; k < KD; k++) s += O[k][i] * e[k];
        g_h[t][i][m] = s;
        ee += e[i] * e[i];
    }
    // log|det G| via unpivoted LU, single logf on pivot product
    float pd = 1.f;
#pragma unroll
    for (int j = 0; j < KD; j++) {
        float piv = O[j][j];
        pd *= piv;
        float ip = 1.f / piv;
#pragma unroll
        for (int r = j + 1; r < KD; r++) {
            float f = O[r][j] * ip;
#pragma unroll
            for (int c = j + 1; c < KD; c++) O[r][c] -= f * O[j][c];
        }
    }
    g_dm[t][m] = -logf(fabsf(pd)) - 4.0f + 0.5f * ee;
}

__device__ __forceinline__ void child_work(int t, int n, const float* __restrict__ muc,
                                           const float* __restrict__ Sc,
                                           const float* __restrict__ Oc) {
    float O[KD][KD], S[KD][KD];
#pragma unroll
    for (int i = 0; i < KD; i++)
#pragma unroll
        for (int j = 0; j < KD; j++) {
            O[i][j] = Oc[n * K2 + i * KD + j];
            S[i][j] = Sc[n * K2 + i * KD + j];
        }
    // in-place unpivoted Gauss-Jordan inverse; product of pivots = det
    float pd = 1.f;
#pragma unroll
    for (int k = 0; k < KD; k++) {
        float piv = O[k][k];
        pd *= piv;
        float ip = 1.f / piv;
#pragma unroll
        for (int i = 0; i < KD; i++) {
            if (i == k) continue;
            float f = O[i][k] * ip;
#pragma unroll
            for (int j = 0; j < KD; j++)
                if (j != k) O[i][j] -= f * O[k][j];
            O[i][k] = -f;
        }
#pragma unroll
        for (int j = 0; j < KD; j++)
            if (j != k) O[k][j] *= ip;
        O[k][k] = ip;
    }
    float lad = logf(fabsf(pd));

    float* out = &g_child[t][n][0];
    // v = Oi * mu
    float mu[KD], v[KD];
#pragma unroll
    for (int i = 0; i < KD; i++) mu[i] = muc[n * KD + i];
#pragma unroll
    for (int i = 0; i < KD; i++) {
        float s = 0.f;
#pragma unroll
        for (int j = 0; j < KD; j++) s += O[i][j] * mu[j];
        v[i] = s;
        out[NPACK + i] = s;
    }
    // Atilde = Oi S Oi^T + v v^T, packed upper (i<=j)
    {
        int p = 0;
#pragma unroll
        for (int i = 0; i < KD; i++) {
            float trow[KD];
#pragma unroll
            for (int c = 0; c < KD; c++) {
                float s = 0.f;
#pragma unroll
                for (int b = 0; b < KD; b++) s += O[i][b] * S[b][c];
                trow[c] = s;
            }
#pragma unroll
            for (int j = i; j < KD; j++) {
                float a = v[i] * v[j];
#pragma unroll
                for (int c = 0; c < KD; c++) a += trow[c] * O[j][c];
                out[p] = a;
                p++;
            }
        }
    }
    // logdet Sigma_c via in-place Cholesky on S, single logf
    float pl = 1.f;
#pragma unroll
    for (int j = 0; j < KD; j++) {
        float s = S[j][j];
#pragma unroll
        for (int k = 0; k < j; k++) s -= S[j][k] * S[j][k];
        float ljj = sqrtf(s);
        S[j][j] = ljj;
        pl *= ljj;
        float inv = 1.f / ljj;
#pragma unroll
        for (int i = j + 1; i < KD; i++) {
            float si = S[i][j];
#pragma unroll
            for (int k = 0; k < j; k++) si -= S[i][k] * S[j][k];
            S[i][j] = si * inv;
        }
    }
    out[NPACK + KD] = lad - logf(pl);
    out[45] = 0.f; out[46] = 0.f; out[47] = 0.f;
}

__global__ __launch_bounds__(32)
void precompute_kernel(const float* __restrict__ mu_p, const float* __restrict__ sigma_p,
                       const float* __restrict__ omega_child,
                       const float* __restrict__ mu_q, const float* __restrict__ sigma_q,
                       const float* __restrict__ omega_parent,
                       const float* __restrict__ mu_r, const float* __restrict__ sigma_r,
                       const float* __restrict__ omega_m_child,
                       const float* __restrict__ mu_s, const float* __restrict__ sigma_s,
                       const float* __restrict__ omega_m_parent) {
    int bid = blockIdx.x;
    int tid = threadIdx.x;
    if (bid == 0 && tid == 0) {
        g_acc[0] = 0.0;
        g_acc[1] = 0.0;
        g_done = 0u;
    }
    if (bid < 8) {
        // parent work: 8 blocks x 32 = 256 = 2 t x 128 m
        int gid = bid * 32 + tid;
        int t = gid >> 7;
        int m = gid & (MM - 1);
        if (t == 0) parent_work(0, m, mu_q, sigma_q, omega_parent);
        else        parent_work(1, m, mu_s, sigma_s, omega_m_parent);
    } else {
        int gid = (bid - 8) * 32 + tid;  // 128 blocks x 32 = 4096 = 2 t x 2048 n
        int t = gid >> 11;
        int n = gid & (NN - 1);
        if (t == 0) child_work(0, n, mu_p, sigma_p, omega_child);
        else        child_work(1, n, mu_r, sigma_r, omega_m_child);
    }
}

// ==================== pair kernel + fused finalize ===========================
__global__ __launch_bounds__(128)
void pair_kernel(const float* __restrict__ W, float* __restrict__ out) {
    const int t = blockIdx.y;
    const int m = threadIdx.x;
    const int n0 = blockIdx.x * NPB;

    // per-m data in registers (45 floats)
    float Bp[NPACK], h[KD], dm;
#pragma unroll
    for (int p = 0; p < NPACK; p++) Bp[p] = g_Bp[t][p][m];
#pragma unroll
    for (int p = 0; p < KD; p++) h[p] = g_h[t][p][m];
    dm = g_dm[t][m];

    // all NPB child records loaded up front (NPB*12 float4 = 48 threads)
    __shared__ float4 ch[NPB][CH_STRIDE / 4];
    if (m < NPB * (CH_STRIDE / 4)) {
        int k = m / (CH_STRIDE / 4);
        int q = m % (CH_STRIDE / 4);
        ch[k][q] = reinterpret_cast<const float4*>(&g_child[t][n0 + k][0])[q];
    }
    __syncthreads();

    double acc = 0.0;
#pragma unroll
    for (int k = 0; k < NPB; k++) {
        float4 r[CH_STRIDE / 4];
#pragma unroll
        for (int q = 0; q < CH_STRIDE / 4; q++) r[q] = ch[k][q];
        const float* A = reinterpret_cast<const float*>(r);

        float kl = dm + A[44];           // dm + c'
#pragma unroll
        for (int p = 0; p < NPACK; p++) kl += Bp[p] * A[p];      // 0.5 tr(B(A+vv^T))
#pragma unroll
        for (int j = 0; j < KD; j++) kl -= h[j] * A[NPACK + j];  // -h.v
        float w = W[(n0 + k) * MM + m];
        acc += (double)(w * kl);
    }

    // block reduction (4 warps)
    __shared__ double wsum[4];
#pragma unroll
    for (int off = 16; off; off >>= 1)
        acc += __shfl_down_sync(0xffffffffu, acc, off);
    if ((m & 31) == 0) wsum[m >> 5] = acc;
    __syncthreads();
    if (m == 0) {
        double bsum = wsum[0] + wsum[1] + wsum[2] + wsum[3];
        atomicAdd(&g_acc[t], bsum);
        __threadfence();
        unsigned int tick = atomicAdd(&g_done, 1u);
        if (tick == 2u * NB - 1u) {
            __threadfence();
            double b  = *((volatile double*)&g_acc[0]);
            double mo = *((volatile double*)&g_acc[1]);
            out[0] = (float)(b + mo);
            out[1] = (float)b;
            out[2] = (float)mo;
        }
    }
}

// ----------------------------------------------------------------------------
extern "C" void kernel_launch(void* const* d_in, const int* in_sizes, int n_in,
                              void* d_out, int out_size) {
    const float* W              = (const float*)d_in[0];
    const float* mu_p           = (const float*)d_in[1];
    const float* sigma_p        = (const float*)d_in[2];
    const float* mu_q_parent    = (const float*)d_in[3];
    const float* sigma_q_parent = (const float*)d_in[4];
    const float* omega_child    = (const float*)d_in[5];
    const float* omega_parent   = (const float*)d_in[6];
    const float* mu_r           = (const float*)d_in[7];
    const float* sigma_r        = (const float*)d_in[8];
    const float* mu_s_parent    = (const float*)d_in[9];
    const float* sigma_s_parent = (const float*)d_in[10];
    const float* omega_m_child  = (const float*)d_in[11];
    const float* omega_m_parent = (const float*)d_in[12];

    precompute_kernel<<<136, 32>>>(mu_p, sigma_p, omega_child,
                                   mu_q_parent, sigma_q_parent, omega_parent,
                                   mu_r, sigma_r, omega_m_child,
                                   mu_s_parent, sigma_s_parent, omega_m_parent);
    pair_kernel<<<dim3(NB, 2), MM>>>(W, (float*)d_out);
}

// round 4
// speedup vs baseline: 4.5439x; 1.0135x over previous
#include <cuda_runtime.h>
#include <math.h>

#define NN 2048
#define MM 128
#define KD 8
#define K2 64
#define NPACK 36          // packed symmetric 8x8 (i<=j)
#define CH_STRIDE 48      // per-child record: 36 Atilde + 8 v + 1 c' + 3 pad
#define NPB 4             // children per block
#define NB (NN / NPB)     // 512 n-chunks per t

// ---------------- scratch (device globals) ----------------------------------
// coef pairs, SoA over m: [0..17] = Bp pairs (0.5 diag / 1.0 offdiag of G^T G),
//                          [18..21] = (-h) pairs where h = G^T e
__device__ unsigned long long g_c2[2][22][MM];
__device__ float g_dm[2][MM];                // -log|det G| - 4 + 0.5 e.e
__device__ float g_child[2][NN][CH_STRIDE];  // [36 Atilde pk][8 v][c'][3 pad]
__device__ double g_part[2][NB];
__device__ unsigned int g_done;

// ---------------- f32x2 helpers ----------------------------------------------
__device__ __forceinline__ unsigned long long pack2(float a, float b) {
    unsigned long long r;
    asm("mov.b64 %0, {%1, %2};" : "=l"(r) : "f"(a), "f"(b));
    return r;
}
__device__ __forceinline__ void ffma2(unsigned long long& d,
                                      unsigned long long a, unsigned long long b) {
    asm("fma.rn.f32x2 %0, %1, %2, %0;" : "+l"(d) : "l"(a), "l"(b));
}
__device__ __forceinline__ float2 unpack2(unsigned long long v) {
    float2 f;
    asm("mov.b64 {%0, %1}, %2;" : "=f"(f.x), "=f"(f.y) : "l"(v));
    return f;
}

// ==================== precompute =============================================
__device__ __forceinline__ void parent_work(int t, int m, const float* __restrict__ mup,
                                            const float* __restrict__ Sp,
                                            const float* __restrict__ Op) {
    float __align__(16) S[KD][KD];
    float __align__(16) O[KD][KD];
    float __align__(16) e[KD];
    {
        const float4* s4 = reinterpret_cast<const float4*>(Sp + (size_t)m * K2);
        const float4* o4 = reinterpret_cast<const float4*>(Op + (size_t)m * K2);
        float4* Sd = reinterpret_cast<float4*>(&S[0][0]);
        float4* Od = reinterpret_cast<float4*>(&O[0][0]);
#pragma unroll
        for (int q = 0; q < 16; q++) { Sd[q] = s4[q]; Od[q] = o4[q]; }
        const float4* m4 = reinterpret_cast<const float4*>(mup + (size_t)m * KD);
        reinterpret_cast<float4*>(e)[0] = m4[0];
        reinterpret_cast<float4*>(e)[1] = m4[1];
    }
    // Cholesky in place (lower triangle of S becomes L)
#pragma unroll
    for (int j = 0; j < KD; j++) {
        float s = S[j][j];
#pragma unroll
        for (int k = 0; k < j; k++) s -= S[j][k] * S[j][k];
        float ljj = sqrtf(s);
        S[j][j] = ljj;
        float inv = 1.f / ljj;
#pragma unroll
        for (int i = j + 1; i < KD; i++) {
            float si = S[i][j];
#pragma unroll
            for (int k = 0; k < j; k++) si -= S[i][k] * S[j][k];
            S[i][j] = si * inv;
        }
    }
    // O := G = L^{-1} O (in place), e := L^{-1} e
#pragma unroll
    for (int i = 0; i < KD; i++) {
        float inv = 1.f / S[i][i];
#pragma unroll
        for (int c = 0; c < KD; c++) {
            float s = O[i][c];
#pragma unroll
            for (int k = 0; k < i; k++) s -= S[i][k] * O[k][c];
            O[i][c] = s * inv;
        }
        float se = e[i];
#pragma unroll
        for (int k = 0; k < i; k++) se -= S[i][k] * e[k];
        e[i] = se * inv;
    }
    // B = G^T G packed (0.5 diag / 1.0 offdiag) -> pairs
    float Bp[NPACK];
    {
        int p = 0;
#pragma unroll
        for (int i = 0; i < KD; i++) {
#pragma unroll
            for (int j = i; j < KD; j++) {
                float b = 0.f;
#pragma unroll
                for (int k = 0; k < KD; k++) b += O[k][i] * O[k][j];
                Bp[p] = (i == j) ? 0.5f * b : b;
                p++;
            }
        }
    }
#pragma unroll
    for (int p = 0; p < 18; p++)
        g_c2[t][p][m] = pack2(Bp[2 * p], Bp[2 * p + 1]);
    // h = G^T e (stored negated), ee = e.e
    float h[KD], ee = 0.f;
#pragma unroll
    for (int i = 0; i < KD; i++) {
        float s = 0.f;
#pragma unroll
        for (int k = 0; k < KD; k++) s += O[k][i] * e[k];
        h[i] = s;
        ee += e[i] * e[i];
    }
#pragma unroll
    for (int q = 0; q < 4; q++)
        g_c2[t][18 + q][m] = pack2(-h[2 * q], -h[2 * q + 1]);
    // log|det G| via unpivoted LU, one logf on pivot product
    float pd = 1.f;
#pragma unroll
    for (int j = 0; j < KD; j++) {
        float piv = O[j][j];
        pd *= piv;
        float ip = 1.f / piv;
#pragma unroll
        for (int r = j + 1; r < KD; r++) {
            float f = O[r][j] * ip;
#pragma unroll
            for (int c = j + 1; c < KD; c++) O[r][c] -= f * O[j][c];
        }
    }
    g_dm[t][m] = -logf(fabsf(pd)) - 4.0f + 0.5f * ee;
}

__device__ __forceinline__ void child_work(int t, int n, const float* __restrict__ muc,
                                           const float* __restrict__ Sc,
                                           const float* __restrict__ Oc) {
    float __align__(16) O[KD][KD];
    float __align__(16) S[KD][KD];
    float __align__(16) mu[KD];
    {
        const float4* s4 = reinterpret_cast<const float4*>(Sc + (size_t)n * K2);
        const float4* o4 = reinterpret_cast<const float4*>(Oc + (size_t)n * K2);
        float4* Sd = reinterpret_cast<float4*>(&S[0][0]);
        float4* Od = reinterpret_cast<float4*>(&O[0][0]);
#pragma unroll
        for (int q = 0; q < 16; q++) { Sd[q] = s4[q]; Od[q] = o4[q]; }
        const float4* m4 = reinterpret_cast<const float4*>(muc + (size_t)n * KD);
        reinterpret_cast<float4*>(mu)[0] = m4[0];
        reinterpret_cast<float4*>(mu)[1] = m4[1];
    }
    // unpivoted Gauss-Jordan inverse in place; product of pivots = det
    float pd = 1.f;
#pragma unroll
    for (int k = 0; k < KD; k++) {
        float piv = O[k][k];
        pd *= piv;
        float ip = 1.f / piv;
#pragma unroll
        for (int i = 0; i < KD; i++) {
            if (i == k) continue;
            float f = O[i][k] * ip;
#pragma unroll
            for (int j = 0; j < KD; j++)
                if (j != k) O[i][j] -= f * O[k][j];
            O[i][k] = -f;
        }
#pragma unroll
        for (int j = 0; j < KD; j++)
            if (j != k) O[k][j] *= ip;
        O[k][k] = ip;
    }
    float lad = logf(fabsf(pd));

    float __align__(16) rec[CH_STRIDE];
    // v = Oi * mu
    float v[KD];
#pragma unroll
    for (int i = 0; i < KD; i++) {
        float s = 0.f;
#pragma unroll
        for (int j = 0; j < KD; j++) s += O[i][j] * mu[j];
        v[i] = s;
        rec[NPACK + i] = s;
    }
    // Atilde = Oi S Oi^T + v v^T, packed upper (i<=j)
    {
        int p = 0;
#pragma unroll
        for (int i = 0; i < KD; i++) {
            float trow[KD];
#pragma unroll
            for (int c = 0; c < KD; c++) {
                float s = 0.f;
#pragma unroll
                for (int b = 0; b < KD; b++) s += O[i][b] * S[b][c];
                trow[c] = s;
            }
#pragma unroll
            for (int j = i; j < KD; j++) {
                float a = v[i] * v[j];
#pragma unroll
                for (int c = 0; c < KD; c++) a += trow[c] * O[j][c];
                rec[p] = a;
                p++;
            }
        }
    }
    // logdet Sigma_c via in-place Cholesky on S, one logf
    float pl = 1.f;
#pragma unroll
    for (int j = 0; j < KD; j++) {
        float s = S[j][j];
#pragma unroll
        for (int k = 0; k < j; k++) s -= S[j][k] * S[j][k];
        float ljj = sqrtf(s);
        S[j][j] = ljj;
        pl *= ljj;
        float inv = 1.f / ljj;
#pragma unroll
        for (int i = j + 1; i < KD; i++) {
            float si = S[i][j];
#pragma unroll
            for (int k = 0; k < j; k++) si -= S[i][k] * S[j][k];
            S[i][j] = si * inv;
        }
    }
    rec[44] = lad - logf(pl);
    rec[45] = 0.f; rec[46] = 0.f; rec[47] = 0.f;

    float4* dst = reinterpret_cast<float4*>(&g_child[t][n][0]);
    const float4* srec = reinterpret_cast<const float4*>(rec);
#pragma unroll
    for (int q = 0; q < CH_STRIDE / 4; q++) dst[q] = srec[q];
}

__global__ __launch_bounds__(32)
void precompute_kernel(const float* __restrict__ mu_p, const float* __restrict__ sigma_p,
                       const float* __restrict__ omega_child,
                       const float* __restrict__ mu_q, const float* __restrict__ sigma_q,
                       const float* __restrict__ omega_parent,
                       const float* __restrict__ mu_r, const float* __restrict__ sigma_r,
                       const float* __restrict__ omega_m_child,
                       const float* __restrict__ mu_s, const float* __restrict__ sigma_s,
                       const float* __restrict__ omega_m_parent) {
    int bid = blockIdx.x;
    int tid = threadIdx.x;
    if (bid == 0 && tid == 0) g_done = 0u;
    if (bid < 8) {
        int gid = bid * 32 + tid;   // 256 = 2 t x 128 m
        int t = gid >> 7;
        int m = gid & (MM - 1);
        if (t == 0) parent_work(0, m, mu_q, sigma_q, omega_parent);
        else        parent_work(1, m, mu_s, sigma_s, omega_m_parent);
    } else {
        int gid = (bid - 8) * 32 + tid;  // 4096 = 2 t x 2048 n
        int t = gid >> 11;
        int n = gid & (NN - 1);
        if (t == 0) child_work(0, n, mu_p, sigma_p, omega_child);
        else        child_work(1, n, mu_r, sigma_r, omega_m_child);
    }
}

// ==================== pair kernel + fused finalize ===========================
__global__ __launch_bounds__(128)
void pair_kernel(const float* __restrict__ W, float* __restrict__ out) {
    const int t = blockIdx.y;
    const int m = threadIdx.x;
    const int n0 = blockIdx.x * NPB;

    unsigned long long c2[22];
#pragma unroll
    for (int p = 0; p < 22; p++) c2[p] = g_c2[t][p][m];
    const float dm = g_dm[t][m];

    float accf = 0.f;
#pragma unroll
    for (int k = 0; k < NPB; k++) {
        const unsigned long long* a2 =
            reinterpret_cast<const unsigned long long*>(&g_child[t][n0 + k][0]);
        unsigned long long acc0 = 0ull, acc1 = 0ull;
#pragma unroll
        for (int p = 0; p < 22; p += 2) {
            ffma2(acc0, c2[p], __ldg(&a2[p]));
            ffma2(acc1, c2[p + 1], __ldg(&a2[p + 1]));
        }
        float2 s0 = unpack2(acc0);
        float2 s1 = unpack2(acc1);
        float cc = g_child[t][n0 + k][44];
        float kl = (s0.x + s0.y) + (s1.x + s1.y) + (dm + cc);
        accf = fmaf(W[(n0 + k) * MM + m], kl, accf);
    }

    // block reduction (4 warps), fp64 from here
    double acc = (double)accf;
#pragma unroll
    for (int off = 16; off; off >>= 1)
        acc += __shfl_down_sync(0xffffffffu, acc, off);
    __shared__ double wsum[4];
    __shared__ int islast;
    if ((m & 31) == 0) wsum[m >> 5] = acc;
    __syncthreads();
    if (m == 0) {
        g_part[t][blockIdx.x] = wsum[0] + wsum[1] + wsum[2] + wsum[3];
        __threadfence();
        unsigned int tick = atomicAdd(&g_done, 1u);
        islast = (tick == 2u * NB - 1u) ? 1 : 0;
    }
    __syncthreads();
    if (islast) {
        __threadfence();
        double s0 = 0.0, s1 = 0.0;
        for (int i = m; i < NB; i += 128) {
            s0 += g_part[0][i];
            s1 += g_part[1][i];
        }
#pragma unroll
        for (int off = 16; off; off >>= 1) {
            s0 += __shfl_down_sync(0xffffffffu, s0, off);
            s1 += __shfl_down_sync(0xffffffffu, s1, off);
        }
        __shared__ double ws0[4], ws1[4];
        if ((m & 31) == 0) { ws0[m >> 5] = s0; ws1[m >> 5] = s1; }
        __syncthreads();
        if (m == 0) {
            double b  = ws0[0] + ws0[1] + ws0[2] + ws0[3];
            double mo = ws1[0] + ws1[1] + ws1[2] + ws1[3];
            out[0] = (float)(b + mo);
            out[1] = (float)b;
            out[2] = (float)mo;
        }
    }
}

// ----------------------------------------------------------------------------
extern "C" void kernel_launch(void* const* d_in, const int* in_sizes, int n_in,
                              void* d_out, int out_size) {
    const float* W              = (const float*)d_in[0];
    const float* mu_p           = (const float*)d_in[1];
    const float* sigma_p        = (const float*)d_in[2];
    const float* mu_q_parent    = (const float*)d_in[3];
    const float* sigma_q_parent = (const float*)d_in[4];
    const float* omega_child    = (const float*)d_in[5];
    const float* omega_parent   = (const float*)d_in[6];
    const float* mu_r           = (const float*)d_in[7];
    const float* sigma_r        = (const float*)d_in[8];
    const float* mu_s_parent    = (const float*)d_in[9];
    const float* sigma_s_parent = (const float*)d_in[10];
    const float* omega_m_child  = (const float*)d_in[11];
    const float* omega_m_parent = (const float*)d_in[12];

    precompute_kernel<<<136, 32>>>(mu_p, sigma_p, omega_child,
                                   mu_q_parent, sigma_q_parent, omega_parent,
                                   mu_r, sigma_r, omega_m_child,
                                   mu_s_parent, sigma_s_parent, omega_m_parent);
    pair_kernel<<<dim3(NB, 2), MM>>>(W, (float*)d_out);
}